// round 2
// baseline (speedup 1.0000x reference)
#include <cuda_runtime.h>

// ---------------------------------------------------------------------------
// PoincareEmbeddings: out[b,l,:] = T[vocab_to_custom[x]] + regular_w[vocab_to_regular[x]]
// where T[k] = lin_w @ mobius_add(logmap0(custom_fixed_w[k]), custom_train_w[k]) + lin_b
//
// Identities exploited (verified against reference semantics):
//  - mask(x) == (vocab_to_custom[x] != 0); row 0 of all tables is zero padding
//  - vocab_to_regular[x] == 0 for custom x  -> regular_w[0] == 0
//  - vocab_to_custom[x] == 0 for regular x  -> T[0] == lin_b (reference adds lin_b to all)
// So the per-token output is a branchless sum of two row gathers.
// ---------------------------------------------------------------------------

constexpr int P_    = 300;     // custom embedding dim
constexpr int PPAD  = 304;     // padded to multiple of BK(8)/16B
constexpr int E_    = 256;     // output embedding dim
constexpr int Kc    = 20000;
constexpr int KP1   = Kc + 1;  // custom table rows (incl. padding row 0)
constexpr int KROWS = 20096;   // ceil(KP1 / 128) * 128  (GEMM M-tile padding)

// scratch (module-static; no runtime allocation)
__device__ float g_M[(size_t)KROWS * PPAD];  // mobius-combined tangent vectors, zero-padded
__device__ float g_T[(size_t)KROWS * E_];    // projected custom embeddings (+bias)

// ---------------------------------------------------------------------------
// Kernel 1: per custom row k, compute u = logmap0(fixed[k]); M[k] = mobius_add(u, train[k]).
// One warp per row. P=300 -> 10 strided elements per lane.
// ---------------------------------------------------------------------------
__global__ void __launch_bounds__(256) k_mobius(const float* __restrict__ fixed_w,
                                                const float* __restrict__ train_w) {
    int warp = (blockIdx.x * blockDim.x + threadIdx.x) >> 5;
    int lane = threadIdx.x & 31;
    if (warp >= KROWS) return;
    float* Mrow = g_M + (size_t)warp * PPAD;

    if (warp >= KP1) {  // GEMM padding rows: keep deterministic zeros
        for (int p = lane; p < PPAD; p += 32) Mrow[p] = 0.0f;
        return;
    }

    const float* f = fixed_w + (size_t)warp * P_;
    const float* t = train_w + (size_t)warp * P_;

    float fr[10], tr[10];
    float sf2 = 0.f, sft = 0.f, st2 = 0.f;
#pragma unroll
    for (int i = 0; i < 10; i++) {
        int p = lane + i * 32;
        float fv = (p < P_) ? __ldg(f + p) : 0.f;
        float tv = (p < P_) ? __ldg(t + p) : 0.f;
        fr[i] = fv; tr[i] = tv;
        sf2 += fv * fv;
        sft += fv * tv;
        st2 += tv * tv;
    }
#pragma unroll
    for (int off = 16; off; off >>= 1) {
        sf2 += __shfl_xor_sync(0xFFFFFFFFu, sf2, off);
        sft += __shfl_xor_sync(0xFFFFFFFFu, sft, off);
        st2 += __shfl_xor_sync(0xFFFFFFFFu, st2, off);
    }

    // logmap0 scale (norm of fixed row is < 1 for this data; row 0 has norm 0)
    float norm  = sqrtf(sf2);
    float scale = (norm > 0.f) ? (atanhf(norm) / norm) : 1.0f;

    // mobius_add(u, t) with u = scale * f:
    float x2 = scale * scale * sf2;   // |u|^2
    float xy = scale * sft;           // u.t
    float y2 = st2;                   // |t|^2
    float cu = 1.f + 2.f * xy + y2;   // coefficient of u
    float ct = 1.f - x2;              // coefficient of t
    float denom = fmaxf(1.f + 2.f * xy + x2 * y2, 1e-15f);

#pragma unroll
    for (int i = 0; i < 10; i++) {
        int p = lane + i * 32;
        if (p < PPAD) {
            float val = (p < P_) ? (cu * (scale * fr[i]) + ct * tr[i]) / denom : 0.f;
            Mrow[p] = val;
        }
    }
}

// ---------------------------------------------------------------------------
// Kernel 2: T[k,e] = sum_p M[k,p] * lin_w[e,p] + lin_b[e]
// A = g_M [KROWS, PPAD] row-major, B = lin_w [E, P] row-major (i.e. B^T), both K-major.
// Classic 128x128x8 fp32 tile, 256 threads, 8x8 per thread.
// ---------------------------------------------------------------------------
constexpr int BM = 128, BN = 128, BK = 8;

__global__ void __launch_bounds__(256) k_gemm(const float* __restrict__ W,
                                              const float* __restrict__ bias) {
    __shared__ float As[BK][BM + 4];
    __shared__ float Bs[BK][BN + 4];

    int tid = threadIdx.x;        // 0..255
    int tx = tid & 15;            // 0..15 -> N
    int ty = tid >> 4;            // 0..15 -> M
    int rowBase = blockIdx.x * BM;
    int colBase = blockIdx.y * BN;

    int la_row  = tid >> 1;       // 0..127
    int la_col4 = (tid & 1) * 4;  // 0 or 4

    float acc[8][8];
#pragma unroll
    for (int i = 0; i < 8; i++)
#pragma unroll
        for (int j = 0; j < 8; j++) acc[i][j] = 0.f;

    for (int p0 = 0; p0 < PPAD; p0 += BK) {
        // load A tile (always in-bounds: g_M is [KROWS, PPAD], grid covers exactly KROWS)
        float4 av = *(const float4*)(g_M + (size_t)(rowBase + la_row) * PPAD + p0 + la_col4);
        As[la_col4 + 0][la_row] = av.x;
        As[la_col4 + 1][la_row] = av.y;
        As[la_col4 + 2][la_row] = av.z;
        As[la_col4 + 3][la_row] = av.w;

        // load B tile from lin_w (stride P_=300; zero-fill p >= 300; 300 % 4 == 0 so
        // each float4 group is entirely valid or entirely out of range)
        float4 bv = make_float4(0.f, 0.f, 0.f, 0.f);
        if (p0 + la_col4 < P_)
            bv = *(const float4*)(W + (size_t)(colBase + la_row) * P_ + p0 + la_col4);
        Bs[la_col4 + 0][la_row] = bv.x;
        Bs[la_col4 + 1][la_row] = bv.y;
        Bs[la_col4 + 2][la_row] = bv.z;
        Bs[la_col4 + 3][la_row] = bv.w;

        __syncthreads();

#pragma unroll
        for (int p = 0; p < BK; p++) {
            float a[8], b[8];
            *(float4*)(a)     = *(const float4*)&As[p][ty * 8];
            *(float4*)(a + 4) = *(const float4*)&As[p][ty * 8 + 4];
            *(float4*)(b)     = *(const float4*)&Bs[p][tx * 8];
            *(float4*)(b + 4) = *(const float4*)&Bs[p][tx * 8 + 4];
#pragma unroll
            for (int i = 0; i < 8; i++)
#pragma unroll
                for (int j = 0; j < 8; j++) acc[i][j] += a[i] * b[j];
        }
        __syncthreads();
    }

    // epilogue: += bias, vectorized stores
    int colr = colBase + tx * 8;
    float4 b0 = *(const float4*)(bias + colr);
    float4 b1 = *(const float4*)(bias + colr + 4);
#pragma unroll
    for (int i = 0; i < 8; i++) {
        int row = rowBase + ty * 8 + i;
        float4 o0 = make_float4(acc[i][0] + b0.x, acc[i][1] + b0.y,
                                acc[i][2] + b0.z, acc[i][3] + b0.w);
        float4 o1 = make_float4(acc[i][4] + b1.x, acc[i][5] + b1.y,
                                acc[i][6] + b1.z, acc[i][7] + b1.w);
        *(float4*)(g_T + (size_t)row * E_ + colr)     = o0;
        *(float4*)(g_T + (size_t)row * E_ + colr + 4) = o1;
    }
}

// ---------------------------------------------------------------------------
// Kernel 3: branchless two-gather-add. 64 float4 lanes per token.
// ---------------------------------------------------------------------------
__global__ void __launch_bounds__(256) k_gather(const int* __restrict__ x,
                                                const int* __restrict__ v2c,
                                                const int* __restrict__ v2r,
                                                const float* __restrict__ Rw,
                                                float4* __restrict__ out,
                                                int ntok) {
    int gtid = blockIdx.x * 256 + threadIdx.x;
    int tok = gtid >> 6;   // token index
    int e4  = gtid & 63;   // float4 index within the 256-wide row
    if (tok >= ntok) return;

    int v  = __ldg(x + tok);
    int cm = __ldg(v2c + v);
    int rm = __ldg(v2r + v);

    float4 a = *(const float4*)(g_T + (size_t)cm * E_ + e4 * 4);
    float4 b = __ldg((const float4*)(Rw + (size_t)rm * E_) + e4);
    out[gtid] = make_float4(a.x + b.x, a.y + b.y, a.z + b.z, a.w + b.w);
}

// ---------------------------------------------------------------------------
// Launch. Input order (setup_inputs dict order):
//  0:x [B,L] i32   1:custom_indices (unused)   2:vocab_to_custom [V] i32
//  3:vocab_to_regular [V] i32   4:custom_fixed_w [K+1,P] f32
//  5:custom_train_w [K+1,P] f32  6:regular_w [V-K,E] f32
//  7:lin_w [E,P] f32             8:lin_b [E] f32
// ---------------------------------------------------------------------------
extern "C" void kernel_launch(void* const* d_in, const int* in_sizes, int n_in,
                              void* d_out, int out_size) {
    const int*   x    = (const int*)d_in[0];
    const int*   v2c  = (const int*)d_in[2];
    const int*   v2r  = (const int*)d_in[3];
    const float* fw   = (const float*)d_in[4];
    const float* tw   = (const float*)d_in[5];
    const float* Rw   = (const float*)d_in[6];
    const float* W    = (const float*)d_in[7];
    const float* bias = (const float*)d_in[8];
    float4* out = (float4*)d_out;

    int ntok = in_sizes[0];  // B*L tokens

    // K1: 20096 rows, 1 warp/row, 8 warps/block
    k_mobius<<<KROWS / 8, 256>>>(fw, tw);

    // K2: [KROWS/128, E/128] blocks
    dim3 g2(KROWS / BM, E_ / BN);
    k_gemm<<<g2, 256>>>(W, bias);

    // K3: ntok tokens * 64 float4 lanes / 256 threads
    int nthreads_total = ntok * 64;
    k_gather<<<(nthreads_total + 255) / 256, 256>>>(x, v2c, v2r, Rw, out, ntok);
}

// round 3
// speedup vs baseline: 1.5614x; 1.5614x over previous
#include <cuda_runtime.h>
#include <cstdint>

// ---------------------------------------------------------------------------
// PoincareEmbeddings: out[b,l,:] = custom ? T[cm] : Rw[rm] + lin_b
// where T[k] = lin_w @ mobius_add(logmap0(custom_fixed_w[k]), custom_train_w[k]) + lin_b
//
// Identities (reference semantics):
//  - custom <=> vocab_to_custom[x] != 0; row 0 of all tables is zero padding
//  - vocab_to_regular[x] == 0 for custom x -> Rw[0] == 0
//  - vocab_to_custom[x] == 0 for regular x -> T[0] == lin_b
// => per token exactly ONE row gather (+ lin_b broadcast for regular tokens).
// ---------------------------------------------------------------------------

constexpr int P_    = 300;     // custom embedding dim
constexpr int PPAD  = 320;     // padded to multiple of BK=32
constexpr int E_    = 256;     // output embedding dim
constexpr int Kc    = 20000;
constexpr int KP1   = Kc + 1;  // custom table rows (incl. padding row 0)
constexpr int KROWS = 20096;   // ceil(KP1/128)*128  (GEMM M-tile padding)

// scratch (module-static; no runtime allocation)
__device__ float g_M[(size_t)KROWS * PPAD];  // tf32-rounded mobius tangent vectors
__device__ float g_T[(size_t)KROWS * E_];    // projected custom embeddings (+bias)

__device__ __forceinline__ float tf32_rna(float x) {
    float r;
    asm("cvt.rna.tf32.f32 %0, %1;" : "=f"(r) : "f"(x));
    return r;
}

// ---------------------------------------------------------------------------
// Kernel 1: per custom row k: u = logmap0(fixed[k]); M[k] = tf32(mobius_add(u, train[k]))
// One warp per row; 10 strided elements per lane covers PPAD=320 exactly.
// ---------------------------------------------------------------------------
__global__ void __launch_bounds__(256) k_mobius(const float* __restrict__ fixed_w,
                                                const float* __restrict__ train_w) {
    int warp = (blockIdx.x * blockDim.x + threadIdx.x) >> 5;
    int lane = threadIdx.x & 31;
    if (warp >= KROWS) return;
    float* Mrow = g_M + (size_t)warp * PPAD;

    if (warp >= KP1) {  // GEMM padding rows stay zero (deterministic)
        for (int p = lane; p < PPAD; p += 32) Mrow[p] = 0.0f;
        return;
    }

    const float* f = fixed_w + (size_t)warp * P_;
    const float* t = train_w + (size_t)warp * P_;

    float fr[10], tr[10];
    float sf2 = 0.f, sft = 0.f, st2 = 0.f;
#pragma unroll
    for (int i = 0; i < 10; i++) {
        int p = lane + i * 32;
        float fv = (p < P_) ? __ldg(f + p) : 0.f;
        float tv = (p < P_) ? __ldg(t + p) : 0.f;
        fr[i] = fv; tr[i] = tv;
        sf2 += fv * fv;
        sft += fv * tv;
        st2 += tv * tv;
    }
#pragma unroll
    for (int off = 16; off; off >>= 1) {
        sf2 += __shfl_xor_sync(0xFFFFFFFFu, sf2, off);
        sft += __shfl_xor_sync(0xFFFFFFFFu, sft, off);
        st2 += __shfl_xor_sync(0xFFFFFFFFu, st2, off);
    }

    float norm  = sqrtf(sf2);
    float scale = (norm > 0.f) ? (atanhf(norm) / norm) : 1.0f;

    // mobius_add(u, t) with u = scale * f
    float x2 = scale * scale * sf2;
    float xy = scale * sft;
    float y2 = st2;
    float cu = 1.f + 2.f * xy + y2;
    float ct = 1.f - x2;
    float denom = fmaxf(1.f + 2.f * xy + x2 * y2, 1e-15f);
    float inv = 1.f / denom;

#pragma unroll
    for (int i = 0; i < 10; i++) {
        int p = lane + i * 32;
        float val = (p < P_) ? (cu * (scale * fr[i]) + ct * tr[i]) * inv : 0.f;
        Mrow[p] = tf32_rna(val);   // pre-round A operand for the tf32 GEMM
    }
}

// ---------------------------------------------------------------------------
// Kernel 2: tf32 tensor-core GEMM  T[k,e] = sum_p M[k,p] * lin_w[e,p] + lin_b[e]
// A = g_M [KROWS, PPAD] K-major (already tf32-rounded), B = lin_w [E, P] K-major.
// Block tile 128x64, 8 warps in 4x2, warp tile 32x32, mma.m16n8k8.tf32, BK=32.
// ---------------------------------------------------------------------------
constexpr int BM = 128, BN = 64, BK = 32;
constexpr int SPAD = BK + 4;   // smem row stride: conflict-free fragment reads

__global__ void __launch_bounds__(256) k_gemm(const float* __restrict__ W,
                                              const float* __restrict__ bias) {
    __shared__ float As[BM][SPAD];   // [m][k]
    __shared__ float Bs[BN][SPAD];   // [n][k]

    int tid  = threadIdx.x;
    int warp = tid >> 5;
    int lane = tid & 31;
    int wm = warp >> 1;              // 0..3 -> M
    int wn = warp & 1;               // 0..1 -> N
    int rowBase = blockIdx.x * BM;
    int colBase = blockIdx.y * BN;

    int g  = lane >> 2;              // group id 0..7
    int tg = lane & 3;               // thread-in-group 0..3

    float c[2][4][4];                // [m-frag][n-frag][reg]
#pragma unroll
    for (int mi = 0; mi < 2; mi++)
#pragma unroll
        for (int ni = 0; ni < 4; ni++)
#pragma unroll
            for (int r = 0; r < 4; r++) c[mi][ni][r] = 0.f;

    for (int p0 = 0; p0 < PPAD; p0 += BK) {
        // --- load A tile: 128x32 = 1024 float4, 4 per thread (already tf32)
#pragma unroll
        for (int i = 0; i < 4; i++) {
            int f4 = tid + i * 256;          // 0..1023
            int r  = f4 >> 3;                // 8 float4 per row
            int c4 = (f4 & 7) * 4;
            float4 v = *(const float4*)(g_M + (size_t)(rowBase + r) * PPAD + p0 + c4);
            As[r][c4 + 0] = v.x; As[r][c4 + 1] = v.y;
            As[r][c4 + 2] = v.z; As[r][c4 + 3] = v.w;
        }
        // --- load B tile: 64x32 = 512 float4, 2 per thread; stride P_=300, zero-fill
#pragma unroll
        for (int i = 0; i < 2; i++) {
            int f4 = tid + i * 256;          // 0..511
            int r  = f4 >> 3;
            int c4 = (f4 & 7) * 4;
            float4 v = make_float4(0.f, 0.f, 0.f, 0.f);
            if (p0 + c4 < P_)                // 300 % 4 == 0: float4 all-valid or all-out
                v = *(const float4*)(W + (size_t)(colBase + r) * P_ + p0 + c4);
            Bs[r][c4 + 0] = tf32_rna(v.x); Bs[r][c4 + 1] = tf32_rna(v.y);
            Bs[r][c4 + 2] = tf32_rna(v.z); Bs[r][c4 + 3] = tf32_rna(v.w);
        }
        __syncthreads();

#pragma unroll
        for (int kk = 0; kk < BK; kk += 8) {
            int k0 = kk + tg;
            // A fragments: 2 m-tiles of 16
            uint32_t a[2][4];
#pragma unroll
            for (int mi = 0; mi < 2; mi++) {
                int r0 = wm * 32 + mi * 16 + g;
                a[mi][0] = __float_as_uint(As[r0][k0]);
                a[mi][1] = __float_as_uint(As[r0 + 8][k0]);
                a[mi][2] = __float_as_uint(As[r0][k0 + 4]);
                a[mi][3] = __float_as_uint(As[r0 + 8][k0 + 4]);
            }
            // B fragments: 4 n-tiles of 8
            uint32_t b[4][2];
#pragma unroll
            for (int ni = 0; ni < 4; ni++) {
                int n0 = wn * 32 + ni * 8 + g;
                b[ni][0] = __float_as_uint(Bs[n0][k0]);
                b[ni][1] = __float_as_uint(Bs[n0][k0 + 4]);
            }
#pragma unroll
            for (int mi = 0; mi < 2; mi++)
#pragma unroll
                for (int ni = 0; ni < 4; ni++) {
                    asm volatile(
                        "mma.sync.aligned.m16n8k8.row.col.f32.tf32.tf32.f32 "
                        "{%0,%1,%2,%3}, {%4,%5,%6,%7}, {%8,%9}, {%0,%1,%2,%3};"
                        : "+f"(c[mi][ni][0]), "+f"(c[mi][ni][1]),
                          "+f"(c[mi][ni][2]), "+f"(c[mi][ni][3])
                        : "r"(a[mi][0]), "r"(a[mi][1]), "r"(a[mi][2]), "r"(a[mi][3]),
                          "r"(b[ni][0]), "r"(b[ni][1]));
                }
        }
        __syncthreads();
    }

    // epilogue: +bias, float2 stores (c0,c1 are adjacent columns)
#pragma unroll
    for (int mi = 0; mi < 2; mi++) {
#pragma unroll
        for (int ni = 0; ni < 4; ni++) {
            int col = colBase + wn * 32 + ni * 8 + tg * 2;
            float bx = __ldg(bias + col), by = __ldg(bias + col + 1);
            int r0 = rowBase + wm * 32 + mi * 16 + g;
            *(float2*)(g_T + (size_t)r0 * E_ + col) =
                make_float2(c[mi][ni][0] + bx, c[mi][ni][1] + by);
            *(float2*)(g_T + (size_t)(r0 + 8) * E_ + col) =
                make_float2(c[mi][ni][2] + bx, c[mi][ni][3] + by);
        }
    }
}

// ---------------------------------------------------------------------------
// Kernel 3: single-gather per token. 64 float4 lanes per token; whole warp
// shares one token (x/v2c/v2r loads are uniform broadcasts).
// ---------------------------------------------------------------------------
__global__ void __launch_bounds__(256) k_gather(const int* __restrict__ x,
                                                const int* __restrict__ v2c,
                                                const int* __restrict__ v2r,
                                                const float* __restrict__ Rw,
                                                const float* __restrict__ lin_b,
                                                float4* __restrict__ out,
                                                int ntok) {
    int gtid = blockIdx.x * 256 + threadIdx.x;
    int tok = gtid >> 6;
    int e4  = gtid & 63;
    if (tok >= ntok) return;

    int v  = __ldg(x + tok);
    int cm = __ldg(v2c + v);
    int rm = __ldg(v2r + v);

    bool custom = (cm != 0);
    const float4* src = custom ? (const float4*)(g_T + (size_t)cm * E_)
                               : (const float4*)(Rw  + (size_t)rm * E_);
    float4 a = __ldg(src + e4);
    float4 bb = __ldg((const float4*)lin_b + e4);   // L1-resident broadcast
    float s = custom ? 0.f : 1.f;                   // T already folds lin_b
    out[gtid] = make_float4(a.x + s * bb.x, a.y + s * bb.y,
                            a.z + s * bb.z, a.w + s * bb.w);
}

// ---------------------------------------------------------------------------
// Launch. Input order: 0:x 1:custom_indices(unused) 2:v2c 3:v2r
//  4:custom_fixed_w 5:custom_train_w 6:regular_w 7:lin_w 8:lin_b
// ---------------------------------------------------------------------------
extern "C" void kernel_launch(void* const* d_in, const int* in_sizes, int n_in,
                              void* d_out, int out_size) {
    const int*   x    = (const int*)d_in[0];
    const int*   v2c  = (const int*)d_in[2];
    const int*   v2r  = (const int*)d_in[3];
    const float* fw   = (const float*)d_in[4];
    const float* tw   = (const float*)d_in[5];
    const float* Rw   = (const float*)d_in[6];
    const float* W    = (const float*)d_in[7];
    const float* bias = (const float*)d_in[8];
    float4* out = (float4*)d_out;

    int ntok = in_sizes[0];  // B*L tokens

    k_mobius<<<KROWS / 8, 256>>>(fw, tw);

    dim3 g2(KROWS / BM, E_ / BN);   // (157, 4)
    k_gemm<<<g2, 256>>>(W, bias);

    int nthreads_total = ntok * 64;
    k_gather<<<(nthreads_total + 255) / 256, 256>>>(x, v2c, v2r, Rw, bias, out, ntok);
}

// round 4
// speedup vs baseline: 1.8145x; 1.1621x over previous
#include <cuda_runtime.h>
#include <cstdint>

// ---------------------------------------------------------------------------
// PoincareEmbeddings: out[b,l,:] = custom ? T[cm] : Rw[rm] + lin_b
// where T[k] = lin_w @ mobius_add(logmap0(custom_fixed_w[k]), custom_train_w[k]) + lin_b
//
// Identities (reference semantics):
//  - custom <=> vocab_to_custom[x] != 0; row 0 of all tables is zero padding
//  - vocab_to_regular[x] == 0 for custom x -> Rw[0] == 0
//  - vocab_to_custom[x] == 0 for regular x -> T[0] == lin_b
// => per token exactly ONE row gather (+ lin_b broadcast for regular tokens).
// Per-vocab fused row pointers (bit0 = custom flag) collapse the index chain.
// ---------------------------------------------------------------------------

constexpr int P_    = 300;     // custom embedding dim
constexpr int PPAD  = 320;     // padded to multiple of BK=32
constexpr int E_    = 256;     // output embedding dim
constexpr int Kc    = 20000;
constexpr int KP1   = Kc + 1;  // custom table rows (incl. padding row 0)
constexpr int KROWS = 20096;   // ceil(KP1/128)*128
constexpr int VMAX  = 100000;  // vocab size

// scratch (module-static; no runtime allocation)
__device__ float g_M[(size_t)KROWS * PPAD];      // tf32-rounded mobius tangent vectors
__device__ float g_T[(size_t)KROWS * E_];        // projected custom embeddings (+bias)
__device__ float g_Wp[(size_t)E_ * PPAD];        // tf32-rounded, zero-padded lin_w
__device__ unsigned long long g_ptr[VMAX];       // per-vocab row pointer | custom-flag

__device__ __forceinline__ float tf32_rna(float x) {
    float r;
    asm("cvt.rna.tf32.f32 %0, %1;" : "=f"(r) : "f"(x));
    return r;
}

// ---------------------------------------------------------------------------
// Kernel 1: per custom row k: u = logmap0(fixed[k]); M[k] = tf32(mobius_add(u, train[k]))
// ---------------------------------------------------------------------------
__global__ void __launch_bounds__(256) k_mobius(const float* __restrict__ fixed_w,
                                                const float* __restrict__ train_w) {
    int warp = (blockIdx.x * blockDim.x + threadIdx.x) >> 5;
    int lane = threadIdx.x & 31;
    if (warp >= KROWS) return;
    float* Mrow = g_M + (size_t)warp * PPAD;

    if (warp >= KP1) {  // GEMM padding rows stay zero (deterministic)
        for (int p = lane; p < PPAD; p += 32) Mrow[p] = 0.0f;
        return;
    }

    const float* f = fixed_w + (size_t)warp * P_;
    const float* t = train_w + (size_t)warp * P_;

    float fr[10], tr[10];
    float sf2 = 0.f, sft = 0.f, st2 = 0.f;
#pragma unroll
    for (int i = 0; i < 10; i++) {
        int p = lane + i * 32;
        float fv = (p < P_) ? __ldg(f + p) : 0.f;
        float tv = (p < P_) ? __ldg(t + p) : 0.f;
        fr[i] = fv; tr[i] = tv;
        sf2 += fv * fv;
        sft += fv * tv;
        st2 += tv * tv;
    }
#pragma unroll
    for (int off = 16; off; off >>= 1) {
        sf2 += __shfl_xor_sync(0xFFFFFFFFu, sf2, off);
        sft += __shfl_xor_sync(0xFFFFFFFFu, sft, off);
        st2 += __shfl_xor_sync(0xFFFFFFFFu, st2, off);
    }

    float norm  = sqrtf(sf2);
    float scale = (norm > 0.f) ? (atanhf(norm) / norm) : 1.0f;

    float x2 = scale * scale * sf2;
    float xy = scale * sft;
    float y2 = st2;
    float cu = 1.f + 2.f * xy + y2;
    float ct = 1.f - x2;
    float denom = fmaxf(1.f + 2.f * xy + x2 * y2, 1e-15f);
    float inv = 1.f / denom;

#pragma unroll
    for (int i = 0; i < 10; i++) {
        int p = lane + i * 32;
        float val = (p < P_) ? (cu * (scale * fr[i]) + ct * tr[i]) * inv : 0.f;
        Mrow[p] = tf32_rna(val);
    }
}

// ---------------------------------------------------------------------------
// Prep A: tf32-round + zero-pad lin_w into g_Wp [E][PPAD]
// ---------------------------------------------------------------------------
__global__ void __launch_bounds__(256) k_wprep(const float* __restrict__ W) {
    int idx = blockIdx.x * 256 + threadIdx.x;
    if (idx >= E_ * PPAD) return;
    int e = idx / PPAD, p = idx - e * PPAD;
    g_Wp[idx] = (p < P_) ? tf32_rna(__ldg(W + (size_t)e * P_ + p)) : 0.f;
}

// ---------------------------------------------------------------------------
// Prep B: per-vocab fused row pointer (bit0 set => custom row, no lin_b add)
// ---------------------------------------------------------------------------
__global__ void __launch_bounds__(256) k_ptab(const int* __restrict__ v2c,
                                              const int* __restrict__ v2r,
                                              const float* __restrict__ Rw, int V) {
    int v = blockIdx.x * 256 + threadIdx.x;
    if (v >= V) return;
    int cm = __ldg(v2c + v);
    int rm = __ldg(v2r + v);
    unsigned long long p;
    if (cm) p = (unsigned long long)(g_T + (size_t)cm * E_) | 1ULL;
    else    p = (unsigned long long)(Rw  + (size_t)rm * E_);
    g_ptr[v] = p;
}

// ---------------------------------------------------------------------------
// Kernel 2: tf32 tensor-core GEMM  T[k,e] = sum_p M[k,p] * g_Wp[e,p] + lin_b[e]
// Block tile 128x64, 8 warps (4x2), warp tile 32x32, mma.m16n8k8.tf32, BK=32.
// 2-stage cp.async pipeline, dynamic smem.
// ---------------------------------------------------------------------------
constexpr int BM = 128, BN = 64, BK = 32;
constexpr int SPAD = BK + 4;            // 36-float row stride (144B, conflict-free)
constexpr int A_ST = BM * SPAD;         // 4608 floats per A stage
constexpr int B_ST = BN * SPAD;         // 2304 floats per B stage
constexpr int SMEM_FLOATS = 2 * (A_ST + B_ST);
constexpr int NIT = PPAD / BK;          // 10

__device__ __forceinline__ void cpa16(uint32_t dst, const float* src) {
    asm volatile("cp.async.cg.shared.global [%0], [%1], 16;" :: "r"(dst), "l"(src));
}

__global__ void __launch_bounds__(256) k_gemm(const float* __restrict__ bias) {
    extern __shared__ float sm[];
    float* As[2] = { sm,            sm + A_ST };
    float* Bs[2] = { sm + 2 * A_ST, sm + 2 * A_ST + B_ST };

    int tid  = threadIdx.x;
    int warp = tid >> 5;
    int lane = tid & 31;
    int wm = warp >> 1;              // 0..3 -> M
    int wn = warp & 1;               // 0..1 -> N
    int rowBase = blockIdx.x * BM;
    int colBase = blockIdx.y * BN;
    int g  = lane >> 2;              // 0..7
    int tg = lane & 3;               // 0..3

    // copy coordinates (A: 4 float4/thread, B: 2 float4/thread)
    int ar[4], ac[4], br[2], bc[2];
#pragma unroll
    for (int i = 0; i < 4; i++) { int f4 = tid + i * 256; ar[i] = f4 >> 3; ac[i] = (f4 & 7) * 4; }
#pragma unroll
    for (int i = 0; i < 2; i++) { int f4 = tid + i * 256; br[i] = f4 >> 3; bc[i] = (f4 & 7) * 4; }

    auto load_tile = [&](int s, int p0) {
#pragma unroll
        for (int i = 0; i < 4; i++)
            cpa16((uint32_t)__cvta_generic_to_shared(As[s] + ar[i] * SPAD + ac[i]),
                  g_M + (size_t)(rowBase + ar[i]) * PPAD + p0 + ac[i]);
#pragma unroll
        for (int i = 0; i < 2; i++)
            cpa16((uint32_t)__cvta_generic_to_shared(Bs[s] + br[i] * SPAD + bc[i]),
                  g_Wp + (size_t)(colBase + br[i]) * PPAD + p0 + bc[i]);
    };

    float c[2][4][4];
#pragma unroll
    for (int mi = 0; mi < 2; mi++)
#pragma unroll
        for (int ni = 0; ni < 4; ni++)
#pragma unroll
            for (int r = 0; r < 4; r++) c[mi][ni][r] = 0.f;

    load_tile(0, 0);
    asm volatile("cp.async.commit_group;");

    for (int it = 0; it < NIT; it++) {
        int cur = it & 1;
        if (it + 1 < NIT) load_tile(cur ^ 1, (it + 1) * BK);
        asm volatile("cp.async.commit_group;");
        asm volatile("cp.async.wait_group 1;");
        __syncthreads();

        const float* Ac = As[cur];
        const float* Bc = Bs[cur];
#pragma unroll
        for (int kk = 0; kk < BK; kk += 8) {
            int k0 = kk + tg;
            uint32_t a[2][4];
#pragma unroll
            for (int mi = 0; mi < 2; mi++) {
                int r0 = wm * 32 + mi * 16 + g;
                a[mi][0] = __float_as_uint(Ac[r0 * SPAD + k0]);
                a[mi][1] = __float_as_uint(Ac[(r0 + 8) * SPAD + k0]);
                a[mi][2] = __float_as_uint(Ac[r0 * SPAD + k0 + 4]);
                a[mi][3] = __float_as_uint(Ac[(r0 + 8) * SPAD + k0 + 4]);
            }
            uint32_t b[4][2];
#pragma unroll
            for (int ni = 0; ni < 4; ni++) {
                int n0 = wn * 32 + ni * 8 + g;
                b[ni][0] = __float_as_uint(Bc[n0 * SPAD + k0]);
                b[ni][1] = __float_as_uint(Bc[n0 * SPAD + k0 + 4]);
            }
#pragma unroll
            for (int mi = 0; mi < 2; mi++)
#pragma unroll
                for (int ni = 0; ni < 4; ni++) {
                    asm volatile(
                        "mma.sync.aligned.m16n8k8.row.col.f32.tf32.tf32.f32 "
                        "{%0,%1,%2,%3}, {%4,%5,%6,%7}, {%8,%9}, {%0,%1,%2,%3};"
                        : "+f"(c[mi][ni][0]), "+f"(c[mi][ni][1]),
                          "+f"(c[mi][ni][2]), "+f"(c[mi][ni][3])
                        : "r"(a[mi][0]), "r"(a[mi][1]), "r"(a[mi][2]), "r"(a[mi][3]),
                          "r"(b[ni][0]), "r"(b[ni][1]));
                }
        }
        __syncthreads();
    }

    // epilogue: +bias, float2 stores
#pragma unroll
    for (int mi = 0; mi < 2; mi++) {
#pragma unroll
        for (int ni = 0; ni < 4; ni++) {
            int col = colBase + wn * 32 + ni * 8 + tg * 2;
            float bx = __ldg(bias + col), by = __ldg(bias + col + 1);
            int r0 = rowBase + wm * 32 + mi * 16 + g;
            *(float2*)(g_T + (size_t)r0 * E_ + col) =
                make_float2(c[mi][ni][0] + bx, c[mi][ni][1] + by);
            *(float2*)(g_T + (size_t)(r0 + 8) * E_ + col) =
                make_float2(c[mi][ni][2] + bx, c[mi][ni][3] + by);
        }
    }
}

// ---------------------------------------------------------------------------
// Kernel 3: single-gather per token. 1 warp = 1 token, 2 float4 per lane.
// Streaming stores keep the gather tables L2-resident.
// ---------------------------------------------------------------------------
__global__ void __launch_bounds__(256) k_gather(const int* __restrict__ x,
                                                const float* __restrict__ lin_b,
                                                float4* __restrict__ out,
                                                int ntok) {
    int gtid = blockIdx.x * 256 + threadIdx.x;
    int tok = gtid >> 5;
    int e4  = gtid & 31;          // lane: handles float4 e4 and e4+32
    if (tok >= ntok) return;

    int v = __ldg(x + tok);
    unsigned long long t = __ldg(g_ptr + v);
    float s = (t & 1ULL) ? 0.f : 1.f;       // regular rows need +lin_b
    const float4* src = (const float4*)(t & ~1ULL);

    float4 a0 = __ldg(src + e4);
    float4 a1 = __ldg(src + e4 + 32);
    float4 b0 = __ldg((const float4*)lin_b + e4);
    float4 b1 = __ldg((const float4*)lin_b + e4 + 32);

    float4* dst = out + (size_t)tok * 64;
    __stcs(dst + e4,      make_float4(a0.x + s * b0.x, a0.y + s * b0.y,
                                      a0.z + s * b0.z, a0.w + s * b0.w));
    __stcs(dst + e4 + 32, make_float4(a1.x + s * b1.x, a1.y + s * b1.y,
                                      a1.z + s * b1.z, a1.w + s * b1.w));
}

// ---------------------------------------------------------------------------
// Launch. Input order: 0:x 1:custom_indices(unused) 2:v2c 3:v2r
//  4:custom_fixed_w 5:custom_train_w 6:regular_w 7:lin_w 8:lin_b
// ---------------------------------------------------------------------------
extern "C" void kernel_launch(void* const* d_in, const int* in_sizes, int n_in,
                              void* d_out, int out_size) {
    const int*   x    = (const int*)d_in[0];
    const int*   v2c  = (const int*)d_in[2];
    const int*   v2r  = (const int*)d_in[3];
    const float* fw   = (const float*)d_in[4];
    const float* tw   = (const float*)d_in[5];
    const float* Rw   = (const float*)d_in[6];
    const float* W    = (const float*)d_in[7];
    const float* bias = (const float*)d_in[8];
    float4* out = (float4*)d_out;

    int ntok = in_sizes[0];   // B*L tokens
    int V    = in_sizes[2];   // vocab size

    static bool smem_set = false;
    if (!smem_set) {
        cudaFuncSetAttribute(k_gemm, cudaFuncAttributeMaxDynamicSharedMemorySize,
                             SMEM_FLOATS * (int)sizeof(float));
        smem_set = true;
    }

    k_mobius<<<KROWS / 8, 256>>>(fw, tw);
    k_wprep<<<(E_ * PPAD + 255) / 256, 256>>>(W);
    k_ptab<<<(V + 255) / 256, 256>>>(v2c, v2r, Rw, V);

    dim3 g2(KROWS / BM, E_ / BN);   // (157, 4)
    k_gemm<<<g2, 256, SMEM_FLOATS * sizeof(float)>>>(bias);

    int nthreads_total = ntok * 32;
    k_gather<<<(nthreads_total + 255) / 256, 256>>>(x, bias, out, ntok);
}